// round 11
// baseline (speedup 1.0000x reference)
#include <cuda_runtime.h>
#include <cuda_bf16.h>

// ListMLE loss with tail term — FINAL converged kernel (10 measured rounds).
// Inputs: output f32 [B,V], target i32 [B], tails i32 [B,T], tail_len i32 [B]
// Output: f32 [B]
//
// Why this shape is optimal on GB300 (sm_103a):
//   - Workload is a mandatory 204.8MB single-pass read; measured device
//     read-stream ceiling is ~5.6TB/s (DRAM busy ~97% of kernel lifetime).
//     Floor = 36.2us + ~1us ramp; this kernel runs 37.3us.
//   - One CTA per row, 256 threads, 7 CTAs/SM -> single co-resident wave.
//   - Simple rolled float4 __ldg stream measured equal-best vs: explicit
//     4-wide batching, __ldcs policy splits, 8x chunking, persistent work
//     stealing, and flat balanced decomposition (all equal or worse).
//   - Tail gathers issued BEFORE the stream (latency hidden under bulk reads).
//   - Warp-parallel epilogue (Kogge-Stone suffix scan of exp(tail), parallel
//     logs, butterfly reductions) -> ~400 exposed cycles on the last CTA.

#define THREADS 256
#define FULL    0xFFFFFFFFu

__global__ __launch_bounds__(THREADS, 7)
void listmle_tail_kernel(const float* __restrict__ output,
                         const int*   __restrict__ target,
                         const int*   __restrict__ tails,
                         const int*   __restrict__ tail_len,
                         float*       __restrict__ out,
                         int V, int T, int nvec, int has_rem)
{
    const int b = blockIdx.x;
    const float* __restrict__ row = output + (size_t)b * (size_t)V;

    extern __shared__ float dyn_sh[];
    float* es_sh = dyn_sh;           // [T] exp(tail scores)
    float* s_sh  = dyn_sh + T;       // [T] raw tail scores
    __shared__ float warpsum[THREADS / 32];

    const int L = min(__ldg(tail_len + b), T);

    // ---- early tail gathers: independent random loads, complete while the
    //      bulk stream below runs; no barrier needed until the epilogue ----
    float tgt = 0.0f;
    if (threadIdx.x == 0) tgt = __ldg(row + __ldg(target + b));
    if (threadIdx.x < T) {
        const int t = threadIdx.x;
        float sv = 0.0f, ev = 0.0f;
        if (t < L) {
            sv = __ldg(row + __ldg(tails + b * T + t));
            ev = __expf(sv);
        }
        s_sh[t]  = sv;
        es_sh[t] = ev;
    }

    // ---- streaming exp-sum (measured-optimal shape) ----
    float acc = 0.0f;
    const float4* __restrict__ row4 = reinterpret_cast<const float4*>(row);
    for (int i = threadIdx.x; i < nvec; i += THREADS) {
        float4 v = __ldg(row4 + i);
        acc += (__expf(v.x) + __expf(v.y)) + (__expf(v.z) + __expf(v.w));
    }
    if (has_rem) {   // V % 4 != 0 only; branch uniform across grid
        for (int j = (nvec << 2) + (int)threadIdx.x; j < V; j += THREADS)
            acc += __expf(__ldg(row + j));
    }

    // ---- per-warp reduce ----
    const int lane = threadIdx.x & 31;
    const int wid  = threadIdx.x >> 5;
    #pragma unroll
    for (int o = 16; o > 0; o >>= 1)
        acc += __shfl_xor_sync(FULL, acc, o);
    if (lane == 0) warpsum[wid] = acc;
    __syncthreads();

    // ---- warp 0: fully parallel epilogue ----
    if (wid == 0) {
        // total = sum of 8 warp partials (butterfly -> every lane)
        float t8 = (lane < THREADS / 32) ? warpsum[lane] : 0.0f;
        #pragma unroll
        for (int o = 16; o > 0; o >>= 1)
            t8 += __shfl_xor_sync(FULL, t8, o);
        const float total = t8;

        // tail elements: lane handles positions lane and lane+32
        float e0 = (lane      < L) ? es_sh[lane]      : 0.0f;
        float e1 = (lane + 32 < L) ? es_sh[lane + 32] : 0.0f;
        float s0 = (lane      < L) ? s_sh[lane]       : 0.0f;
        float s1 = (lane + 32 < L) ? s_sh[lane + 32]  : 0.0f;

        // inclusive SUFFIX scans within each 32-block (Kogge-Stone, shfl_down)
        float S1 = e1;
        #pragma unroll
        for (int o = 1; o < 32; o <<= 1) {
            float y = __shfl_down_sync(FULL, S1, o);
            if (lane + o < 32) S1 += y;
        }
        float S0 = e0;
        #pragma unroll
        for (int o = 1; o < 32; o <<= 1) {
            float y = __shfl_down_sync(FULL, S0, o);
            if (lane + o < 32) S0 += y;
        }
        const float sum_upper = __shfl_sync(FULL, S1, 0);  // sum of e[32..]
        S0 += sum_upper;                                   // global suffix sums
        const float sum_es = __shfl_sync(FULL, S0, 0);     // sum of all exp(s)

        // above = sum of raw tail scores
        float ab = s0 + s1;
        #pragma unroll
        for (int o = 16; o > 0; o >>= 1)
            ab += __shfl_xor_sync(FULL, ab, o);

        const float tgt_b  = __shfl_sync(FULL, tgt, 0);
        const float others = total - __expf(tgt_b) - sum_es;

        // below = sum over valid positions of log(suffix_sum + others)
        float lg = 0.0f;
        if (lane      < L) lg += __logf(S0 + others);
        if (lane + 32 < L) lg += __logf(S1 + others);
        #pragma unroll
        for (int o = 16; o > 0; o >>= 1)
            lg += __shfl_xor_sync(FULL, lg, o);

        if (lane == 0) {
            const float log_pl    = tgt_b - __logf(total);
            const float tail_term = (L > 0) ? (ab - lg) : 0.0f;
            out[b] = -(log_pl + tail_term);
        }
    }
}

extern "C" void kernel_launch(void* const* d_in, const int* in_sizes, int n_in,
                              void* d_out, int out_size)
{
    const float* output   = (const float*)d_in[0];
    const int*   target   = (const int*)  d_in[1];
    const int*   tails    = (const int*)  d_in[2];
    const int*   tail_len = (const int*)  d_in[3];
    float*       out      = (float*)      d_out;

    const int B = in_sizes[1];             // 1024
    const int V = in_sizes[0] / B;         // 50000
    const int T = in_sizes[2] / B;         // 50

    const int nvec    = V >> 2;
    const int has_rem = (V & 3) ? 1 : 0;

    const size_t shmem = 2 * (size_t)T * sizeof(float);
    listmle_tail_kernel<<<B, THREADS, shmem>>>(
        output, target, tails, tail_len, out, V, T, nvec, has_rem);
}

// round 12
// speedup vs baseline: 1.0026x; 1.0026x over previous
#include <cuda_runtime.h>
#include <cuda_bf16.h>

// ListMLE loss with tail term.
// Inputs: output f32 [B,V], target i32 [B], tails i32 [B,T], tail_len i32 [B]
// Output: f32 [B]
//
// Converged structure (11 rounds): one CTA per row, 256 threads, 7 CTAs/SM
// single wave, streaming float4 exp-sum at the measured device read ceiling
// (~5.6TB/s), early tail gathers, warp-parallel epilogue.
//
// R11 variation: warp-contiguous segmentation — each warp streams a
// contiguous ~25KB segment of the row (sequential 512B lines) instead of
// interleaving all 8 warps across 16KB windows. Maximizes HBM row-buffer
// locality; everything else identical to the measured optimum.

#define THREADS 256
#define NWARPS  (THREADS / 32)
#define FULL    0xFFFFFFFFu

__global__ __launch_bounds__(THREADS, 7)
void listmle_tail_kernel(const float* __restrict__ output,
                         const int*   __restrict__ target,
                         const int*   __restrict__ tails,
                         const int*   __restrict__ tail_len,
                         float*       __restrict__ out,
                         int V, int T, int nvec, int has_rem)
{
    const int b = blockIdx.x;
    const float* __restrict__ row = output + (size_t)b * (size_t)V;

    extern __shared__ float dyn_sh[];
    float* es_sh = dyn_sh;           // [T] exp(tail scores)
    float* s_sh  = dyn_sh + T;       // [T] raw tail scores
    __shared__ float warpsum[NWARPS];

    const int lane = threadIdx.x & 31;
    const int wid  = threadIdx.x >> 5;

    const int L = min(__ldg(tail_len + b), T);

    // ---- early tail gathers: independent random loads, complete while the
    //      bulk stream below runs ----
    float tgt = 0.0f;
    if (threadIdx.x == 0) tgt = __ldg(row + __ldg(target + b));
    if (threadIdx.x < T) {
        const int t = threadIdx.x;
        float sv = 0.0f, ev = 0.0f;
        if (t < L) {
            sv = __ldg(row + __ldg(tails + b * T + t));
            ev = __expf(sv);
        }
        s_sh[t]  = sv;
        es_sh[t] = ev;
    }

    // ---- streaming exp-sum: warp-contiguous segments ----
    // warp w owns float4 range [w*seg, min((w+1)*seg, nvec)); lanes stride 32
    // within the segment -> each iteration is one contiguous 512B line.
    const int seg = (nvec + NWARPS - 1) / NWARPS;
    const int wlo = wid * seg;
    const int whi = min(wlo + seg, nvec);

    float acc = 0.0f;
    const float4* __restrict__ row4 = reinterpret_cast<const float4*>(row);
    for (int i = wlo + lane; i < whi; i += 32) {
        float4 v = __ldg(row4 + i);
        acc += (__expf(v.x) + __expf(v.y)) + (__expf(v.z) + __expf(v.w));
    }
    if (has_rem) {   // V % 4 != 0 only; uniform branch
        for (int j = (nvec << 2) + (int)threadIdx.x; j < V; j += THREADS)
            acc += __expf(__ldg(row + j));
    }

    // ---- per-warp reduce ----
    #pragma unroll
    for (int o = 16; o > 0; o >>= 1)
        acc += __shfl_xor_sync(FULL, acc, o);
    if (lane == 0) warpsum[wid] = acc;
    __syncthreads();

    // ---- warp 0: fully parallel epilogue ----
    if (wid == 0) {
        // total = sum of 8 warp partials (butterfly -> every lane)
        float t8 = (lane < NWARPS) ? warpsum[lane] : 0.0f;
        #pragma unroll
        for (int o = 16; o > 0; o >>= 1)
            t8 += __shfl_xor_sync(FULL, t8, o);
        const float total = t8;

        // tail elements: lane handles positions lane and lane+32
        float e0 = (lane      < L) ? es_sh[lane]      : 0.0f;
        float e1 = (lane + 32 < L) ? es_sh[lane + 32] : 0.0f;
        float s0 = (lane      < L) ? s_sh[lane]       : 0.0f;
        float s1 = (lane + 32 < L) ? s_sh[lane + 32]  : 0.0f;

        // inclusive SUFFIX scans within each 32-block (Kogge-Stone, shfl_down)
        float S1 = e1;
        #pragma unroll
        for (int o = 1; o < 32; o <<= 1) {
            float y = __shfl_down_sync(FULL, S1, o);
            if (lane + o < 32) S1 += y;
        }
        float S0 = e0;
        #pragma unroll
        for (int o = 1; o < 32; o <<= 1) {
            float y = __shfl_down_sync(FULL, S0, o);
            if (lane + o < 32) S0 += y;
        }
        const float sum_upper = __shfl_sync(FULL, S1, 0);  // sum of e[32..]
        S0 += sum_upper;                                   // global suffix sums
        const float sum_es = __shfl_sync(FULL, S0, 0);     // sum of all exp(s)

        // above = sum of raw tail scores
        float ab = s0 + s1;
        #pragma unroll
        for (int o = 16; o > 0; o >>= 1)
            ab += __shfl_xor_sync(FULL, ab, o);

        const float tgt_b  = __shfl_sync(FULL, tgt, 0);
        const float others = total - __expf(tgt_b) - sum_es;

        // below = sum over valid positions of log(suffix_sum + others)
        float lg = 0.0f;
        if (lane      < L) lg += __logf(S0 + others);
        if (lane + 32 < L) lg += __logf(S1 + others);
        #pragma unroll
        for (int o = 16; o > 0; o >>= 1)
            lg += __shfl_xor_sync(FULL, lg, o);

        if (lane == 0) {
            const float log_pl    = tgt_b - __logf(total);
            const float tail_term = (L > 0) ? (ab - lg) : 0.0f;
            out[b] = -(log_pl + tail_term);
        }
    }
}

extern "C" void kernel_launch(void* const* d_in, const int* in_sizes, int n_in,
                              void* d_out, int out_size)
{
    const float* output   = (const float*)d_in[0];
    const int*   target   = (const int*)  d_in[1];
    const int*   tails    = (const int*)  d_in[2];
    const int*   tail_len = (const int*)  d_in[3];
    float*       out      = (float*)      d_out;

    const int B = in_sizes[1];             // 1024
    const int V = in_sizes[0] / B;         // 50000
    const int T = in_sizes[2] / B;         // 50

    const int nvec    = V >> 2;
    const int has_rem = (V & 3) ? 1 : 0;

    const size_t shmem = 2 * (size_t)T * sizeof(float);
    listmle_tail_kernel<<<B, THREADS, shmem>>>(
        output, target, tails, tail_len, out, V, T, nvec, has_rem);
}